// round 13
// baseline (speedup 1.0000x reference)
#include <cuda_runtime.h>
#include <math.h>

// Problem dims (fixed by the dataset)
#define NB 4
#define CC 256
#define TT 16
#define HH 56
#define WW 56
#define KK 16
#define TP 8
#define HP 28
#define WP 28
#define PLANE (TT*HH*WW)        // 50176, channel stride in vw
#define OPLANE (TP*HP*WP)       // 6272, channel stride in out
#define SPLANE (HH*WW)          // 3136 spatial points per (n,t)
#define PL2 (PLANE/2)           // channel stride in 8-byte units

// Scratch: exp map, [N, T, H, W]
__device__ float g_emap[NB * TT * HH * WW];

__device__ __forceinline__ unsigned long long fma2(unsigned long long a,
                                                   unsigned long long b,
                                                   unsigned long long c) {
    unsigned long long d;
    asm("fma.rn.f32x2 %0, %1, %2, %3;" : "=l"(d) : "l"(a), "l"(b), "l"(c));
    return d;
}

__device__ __forceinline__ unsigned long long add2(unsigned long long a,
                                                   unsigned long long b) {
    unsigned long long d;
    asm("add.rn.f32x2 %0, %1, %2;" : "=l"(d) : "l"(a), "l"(b));
    return d;
}

__device__ __forceinline__ float lo32(unsigned long long v) {
    return __uint_as_float((unsigned)v);
}
__device__ __forceinline__ float hi32(unsigned long long v) {
    return __uint_as_float((unsigned)(v >> 32));
}

// ---------------------------------------------------------------------------
// Kernel 1: emap[n,t,h,w] = exp( max_k( sum_c w[n,k,c]*vw[n,c,t,h,w] ) / 16 )
// CHANNEL-SPLIT across warp pairs: warps (2s, 2s+1) own channel halves
// [0,128)/[128,256) of the same 16-pair strip (distinct data -> no extra
// DRAM or LDG issue), plus the proven half-warp K-split within each warp.
// Per-lane state: acc[8] + x[8] ULL ~= 44 regs -> fits the 48-reg cap at
// (448,3) => 42 warps/SM (66% occ), 8 outstanding LDG.64 per lane.
// Channel-half partials summed via a 14KB smem exchange (add.rn.f32x2),
// then khalf merged by shfl_xor(16).
// block (32,14) = 7 strips x 2 chalf; grid (14,16,4): 14 blocks x 112
// pairs = 1568 pairs per (n,t) plane.
// ---------------------------------------------------------------------------
__global__ __launch_bounds__(448, 3) void emap_kernel(const float* __restrict__ vw,
                                                      const float* __restrict__ wmat) {
    __shared__ unsigned long long wsp[CC * KK];      // [c][k] {s,s} packed, 32KB
    __shared__ unsigned long long xch[7][32][8];     // chalf=1 partials, 14KB

    const int n = blockIdx.z;
    const int t = blockIdx.y;
    const int tid = threadIdx.y * 32 + threadIdx.x;

    // Load weights for this n into smem, duplicated into both f32x2 halves.
    const float* wn = wmat + (size_t)n * KK * CC;   // layout [k][c]
    for (int j = tid; j < KK * CC; j += 448) {
        int k = j >> 8;        // j = k*256 + c
        int c = j & 255;
        unsigned int si = __float_as_uint(wn[j]);
        wsp[c * KK + k] = ((unsigned long long)si << 32) | si;
    }
    __syncthreads();

    const int lane  = threadIdx.x;
    const int khalf = lane >> 4;                       // 0/1: k 0-7 / 8-15
    const int li    = lane & 15;
    const int strip = threadIdx.y >> 1;                // 0..6
    const int chalf = threadIdx.y & 1;                 // 0/1: c 0-127 / 128-255
    const int pair  = (blockIdx.x * 7 + strip) * 16 + li;   // 0..1567

    // start at channel chalf*128
    size_t base = (((size_t)n * CC + chalf * (CC / 2)) * TT + t) * SPLANE + 2 * pair;
    const unsigned long long* src = (const unsigned long long*)(vw + base);

    unsigned long long acc[8];
#pragma unroll
    for (int k = 0; k < 8; k++) acc[k] = 0ull;

    const ulonglong2* wv = (const ulonglong2*)wsp;
    const int cwbase = chalf * (CC / 2);

    for (int c0 = 0; c0 < CC / 2; c0 += 8) {
        unsigned long long x[8];
#pragma unroll
        for (int u = 0; u < 8; u++)
            x[u] = __ldg(src + (size_t)u * PL2);
        src += 8 * (size_t)PL2;
#pragma unroll
        for (int u = 0; u < 8; u++) {
            const int cw = (cwbase + c0 + u) * (KK / 2) + khalf * 4;
            ulonglong2 wp0 = wv[cw + 0];
            ulonglong2 wp1 = wv[cw + 1];
            acc[0] = fma2(wp0.x, x[u], acc[0]);
            acc[1] = fma2(wp0.y, x[u], acc[1]);
            acc[2] = fma2(wp1.x, x[u], acc[2]);
            acc[3] = fma2(wp1.y, x[u], acc[3]);
            ulonglong2 wp2 = wv[cw + 2];
            ulonglong2 wp3 = wv[cw + 3];
            acc[4] = fma2(wp2.x, x[u], acc[4]);
            acc[5] = fma2(wp2.y, x[u], acc[5]);
            acc[6] = fma2(wp3.x, x[u], acc[6]);
            acc[7] = fma2(wp3.y, x[u], acc[7]);
        }
    }

    // Sum the two channel halves: odd warps publish, even warps reduce.
    if (chalf == 1) {
#pragma unroll
        for (int k = 0; k < 8; k++) xch[strip][lane][k] = acc[k];
    }
    __syncthreads();
    if (chalf == 0) {
#pragma unroll
        for (int k = 0; k < 8; k++) acc[k] = add2(acc[k], xch[strip][lane][k]);

        float m0 = -3.4e38f, m1 = -3.4e38f;
#pragma unroll
        for (int k = 0; k < 8; k++) {
            m0 = fmaxf(m0, lo32(acc[k]));
            m1 = fmaxf(m1, hi32(acc[k]));
        }
        // merge k halves (lane li <-> li+16 hold the same pair)
        m0 = fmaxf(m0, __shfl_xor_sync(0xffffffffu, m0, 16));
        m1 = fmaxf(m1, __shfl_xor_sync(0xffffffffu, m1, 16));

        if (khalf == 0) {
            // sqrt(C) = 16 exactly
            size_t eidx = ((size_t)n * TT + t) * SPLANE + 2 * pair;
            *(float2*)(g_emap + eidx) =
                make_float2(expf(m0 * 0.0625f), expf(m1 * 0.0625f));
        }
    }
}

// ---------------------------------------------------------------------------
// Kernel 2 (R8 structure — best measured pool, near DRAM roofline): lane owns
// output pair (2w2, 2w2+1); one LDG.128 per row per channel; the w-1 corner
// term comes from the left lane via one shfl_up per channel after the r-loop.
// grid (HP, TP, NB*2), block (32,8).
// ---------------------------------------------------------------------------
__global__ __launch_bounds__(256, 4) void pool_kernel(const float* __restrict__ vw,
                                                      float* __restrict__ out) {
    const int n     = blockIdx.z >> 1;
    const int chalf = blockIdx.z & 1;
    const int tp = blockIdx.y;
    const int hp = blockIdx.x;
    const int tid = threadIdx.y * 32 + threadIdx.x;

    __shared__ float4 wpk[9 * 14];   // {e[4w2], e[4w2+1], e[4w2+2], e[4w2+3]} per (r,w2)
    __shared__ float  wem[9 * 14];   // e[4w2-1]  (denominator only)
    __shared__ float  wrd[14 * 2];   // 1/denominator for outputs (2w2, 2w2+1)

    // Fill window-weight tables (126 items).
    if (tid < 126) {
        const int r  = tid / 14;
        const int w2 = tid - r * 14;
        const int dt = r / 3, dh = r - dt * 3;
        const int t = 2 * tp - 1 + dt;
        const int h = 2 * hp - 1 + dh;
        const bool rv = (t >= 0) && (h >= 0);
        const int tc = t > 0 ? t : 0;
        const int hc = h > 0 ? h : 0;
        const float* ep = g_emap + ((size_t)n * TT + tc) * SPLANE + (size_t)hc * WW;
        const int wb = 4 * w2;
        float em1 = (rv && wb > 0) ? ep[wb - 1] : 0.f;
        float e0 = rv ? ep[wb + 0] : 0.f;
        float e1 = rv ? ep[wb + 1] : 0.f;
        float e2 = rv ? ep[wb + 2] : 0.f;
        float e3 = rv ? ep[wb + 3] : 0.f;
        wpk[tid] = make_float4(e0, e1, e2, e3);
        wem[tid] = em1;
    }
    __syncthreads();
    if (tid < 28) {
        const int w2i = tid % 14;
        const int sel = tid / 14;
        float s = 0.f;
#pragma unroll
        for (int r = 0; r < 9; r++) {
            float4 f = wpk[r * 14 + w2i];
            s += sel ? (f.y + f.z + f.w) : (wem[r * 14 + w2i] + f.x + f.y);
        }
        wrd[w2i * 2 + sel] = 1.0f / s;
    }
    __syncthreads();

    const int lane = threadIdx.x;
    const int w2   = (lane & 15) < 14 ? (lane & 15) : 13;  // clamp
    const int csel = lane >> 4;                            // channel select 0/1
    const bool act = (lane & 15) < 14;

    const float rden0 = wrd[w2 * 2 + 0];
    const float rden1 = wrd[w2 * 2 + 1];

    int rowoff[9];
#pragma unroll
    for (int r = 0; r < 9; r++) {
        const int dt = r / 3, dh = r - dt * 3;
        const int t = 2 * tp - 1 + dt;
        const int h = 2 * hp - 1 + dh;
        const int tc = t > 0 ? t : 0;
        const int hc = h > 0 ? h : 0;
        rowoff[r] = (tc * HH + hc) * WW;
    }

    const float* basep = vw + (size_t)n * CC * PLANE + 4 * w2;
    float* outbase = out + (((size_t)n * CC * TP + tp) * HP + hp) * WP + 2 * w2;

    const int cbeg = chalf * (CC / 2);
    const ulonglong2* wpk2 = (const ulonglong2*)wpk;

    // 4 channels per warp-iteration: this lane handles cA=c0+2*csel, cB=cA+1.
    for (int c0 = cbeg + threadIdx.y * 4; c0 < cbeg + CC / 2; c0 += 32) {
        const int cA = c0 + 2 * csel;
        const float* pA = basep + (size_t)cA * PLANE;
        const float* pB = pA + PLANE;
        unsigned long long a0A = 0ull, a1A = 0ull, a0B = 0ull, a1B = 0ull;
        float sxA = 0.f, spA = 0.f, sxB = 0.f, spB = 0.f;
#pragma unroll
        for (int r = 0; r < 9; r++) {
            ulonglong2 xA = __ldg((const ulonglong2*)(pA + rowoff[r]));
            ulonglong2 xB = __ldg((const ulonglong2*)(pB + rowoff[r]));
            ulonglong2 wpr = wpk2[r * 14 + w2];   // .x = (e0,e1), .y = (e2,e3)
            a0A = fma2(wpr.x, xA.x, a0A);
            a1A = fma2(wpr.y, xA.y, a1A);
            a0B = fma2(wpr.x, xB.x, a0B);
            a1B = fma2(wpr.y, xB.y, a1B);
            sxA = fmaf(hi32(wpr.x), hi32(xA.x), sxA);   // e1*v1 -> own out1
            spA = fmaf(hi32(wpr.y), hi32(xA.y), spA);   // e3*v3 -> right nbr out0
            sxB = fmaf(hi32(wpr.x), hi32(xB.x), sxB);
            spB = fmaf(hi32(wpr.y), hi32(xB.y), spB);
        }
        float spAm = __shfl_up_sync(0xffffffffu, spA, 1);
        float spBm = __shfl_up_sync(0xffffffffu, spB, 1);
        if ((lane & 15) == 0) { spAm = 0.f; spBm = 0.f; }
        if (act) {
            float2 oA = make_float2((lo32(a0A) + hi32(a0A) + spAm) * rden0,
                                    (lo32(a1A) + hi32(a1A) + sxA) * rden1);
            float2 oB = make_float2((lo32(a0B) + hi32(a0B) + spBm) * rden0,
                                    (lo32(a1B) + hi32(a1B) + sxB) * rden1);
            *(float2*)(outbase + (size_t)cA * OPLANE) = oA;
            *(float2*)(outbase + (size_t)(cA + 1) * OPLANE) = oB;
        }
    }
}

extern "C" void kernel_launch(void* const* d_in, const int* in_sizes, int n_in,
                              void* d_out, int out_size) {
    const float* a0 = (const float*)d_in[0];
    const float* a1 = (const float*)d_in[1];
    // vw is the big tensor (51,380,224 elems); w is 16,384 elems.
    const float* vw   = (in_sizes[0] > in_sizes[1]) ? a0 : a1;
    const float* wmat = (in_sizes[0] > in_sizes[1]) ? a1 : a0;
    float* out = (float*)d_out;

    emap_kernel<<<dim3(14, TT, NB), dim3(32, 14)>>>(vw, wmat);
    pool_kernel<<<dim3(HP, TP, NB * 2), dim3(32, 8)>>>(vw, out);
}

// round 14
// speedup vs baseline: 1.3386x; 1.3386x over previous
#include <cuda_runtime.h>
#include <math.h>

// Problem dims (fixed by the dataset)
#define NB 4
#define CC 256
#define TT 16
#define HH 56
#define WW 56
#define KK 16
#define TP 8
#define HP 28
#define WP 28
#define PLANE (TT*HH*WW)        // 50176, channel stride in vw
#define OPLANE (TP*HP*WP)       // 6272, channel stride in out
#define SPLANE (HH*WW)          // 3136 spatial points per (n,t)

// Scratch: exp map, [N, T, H, W]
__device__ float g_emap[NB * TT * HH * WW];

__device__ __forceinline__ unsigned long long fma2(unsigned long long a,
                                                   unsigned long long b,
                                                   unsigned long long c) {
    unsigned long long d;
    asm("fma.rn.f32x2 %0, %1, %2, %3;" : "=l"(d) : "l"(a), "l"(b), "l"(c));
    return d;
}

__device__ __forceinline__ float lo32(unsigned long long v) {
    return __uint_as_float((unsigned)v);
}
__device__ __forceinline__ float hi32(unsigned long long v) {
    return __uint_as_float((unsigned)(v >> 32));
}

__device__ __forceinline__ unsigned tf32_rna(float x) {
    unsigned r;
    asm("cvt.rna.tf32.f32 %0, %1;" : "=r"(r) : "f"(x));
    return r;
}

// D(16x8) += A(16x8) * B(8x8), tf32 inputs, f32 accum.
__device__ __forceinline__ void mma8(float* d, const unsigned* a,
                                     unsigned b0, unsigned b1) {
    asm("mma.sync.aligned.m16n8k8.row.col.f32.tf32.tf32.f32 "
        "{%0,%1,%2,%3}, {%4,%5,%6,%7}, {%8,%9}, {%0,%1,%2,%3};"
        : "+f"(d[0]), "+f"(d[1]), "+f"(d[2]), "+f"(d[3])
        : "r"(a[0]), "r"(a[1]), "r"(a[2]), "r"(a[3]), "r"(b0), "r"(b1));
}

// ---------------------------------------------------------------------------
// Kernel 1: emap[n,t,h,w] = exp( max_k( sum_c w[n,k,c]*vw[n,c,t,h,w] ) / 16 )
// TENSOR-CORE PATH: the dot products are the GEMM D[m,k] = vw^T[m,c] w^T[c,k]
// with M=3136/plane, N=16 words, K=256 channels, computed with
// mma.sync.m16n8k8 tf32. Precision: each operand split hi+lo via cvt.rna.tf32
// and 3 MMAs (ah*bh + al*bh + ah*bl) -> fp32-quality results.
// Per warp: 64 consecutive spatial positions = 2 passes x 2 m16 tiles;
// per c-step (8 channels): 8 LDG.32 (A frags, sector-aligned 32B runs),
// 2 LDS.128 (B frags pre-staged in fragment order), 12 MMA.
// Epilogue: lane-local max over its 8 D values per row + shfl_xor(1,2),
// exp, store. block (32,7), grid (7,16,4) = 448 blocks, (224,4) -> 73-reg
// budget, 28 warps/SM, single wave.
// ---------------------------------------------------------------------------
__global__ __launch_bounds__(224, 4) void emap_kernel(const float* __restrict__ vw,
                                                      const float* __restrict__ wmat) {
    // [step s][n-half h][lane] = {b0h, b1h, b0l, b1l}; b0 = B[k=8s+t][n=8h+g]
    __shared__ uint4 bfrag[32 * 2 * 32];   // 32 KB

    const int n  = blockIdx.z;
    const int tt = blockIdx.y;
    const int tid = threadIdx.y * 32 + threadIdx.x;

    // Stage w (layout [k_word][c]) into fragment order with hi/lo tf32 split.
    const float* wn = wmat + (size_t)n * KK * CC;
    for (int j = tid; j < 2048; j += 224) {
        const int s = j >> 6;
        const int h = (j >> 5) & 1;
        const int l = j & 31;
        const int tg = l & 3, gg = l >> 2;
        const int kw = 8 * h + gg;        // word index (n of GEMM)
        const int c  = 8 * s + tg;        // channel (k of GEMM)
        float b0 = wn[kw * CC + c];
        float b1 = wn[kw * CC + c + 4];
        unsigned b0h = tf32_rna(b0), b1h = tf32_rna(b1);
        unsigned b0l = tf32_rna(b0 - __uint_as_float(b0h));
        unsigned b1l = tf32_rna(b1 - __uint_as_float(b1h));
        bfrag[j] = make_uint4(b0h, b1h, b0l, b1l);
    }
    __syncthreads();

    const int lane = threadIdx.x;
    const int t = lane & 3;           // threadID in group (col of A, row of B)
    const int g = lane >> 2;          // group (row of A, col of B)
    const int mwarp = (blockIdx.x * 7 + threadIdx.y) * 64;  // warp's 64 positions
    const size_t base_nt = (size_t)n * CC * PLANE + (size_t)tt * SPLANE;
    const size_t eb = ((size_t)n * TT + tt) * SPLANE;

#pragma unroll
    for (int pass = 0; pass < 2; pass++) {
        const int m0 = mwarp + 32 * pass;
        const float* pa = vw + base_nt + (size_t)t * PLANE + m0 + g;

        float D[2][2][4];   // [tile][n-half][frag]
#pragma unroll
        for (int i = 0; i < 2; i++)
#pragma unroll
            for (int h = 0; h < 2; h++)
#pragma unroll
                for (int e = 0; e < 4; e++) D[i][h][e] = 0.f;

        for (int s = 0; s < 32; s++) {
            // A fragments (raw f32): a0=(g,t) a1=(g+8,t) a2=(g,t+4) a3=(g+8,t+4)
            float araw[2][4];
            araw[0][0] = pa[0];
            araw[0][1] = pa[8];
            araw[0][2] = pa[4 * PLANE];
            araw[0][3] = pa[4 * PLANE + 8];
            araw[1][0] = pa[16];
            araw[1][1] = pa[24];
            araw[1][2] = pa[4 * PLANE + 16];
            araw[1][3] = pa[4 * PLANE + 24];
            pa += 8 * (size_t)PLANE;

            unsigned ah[2][4], al[2][4];
#pragma unroll
            for (int i = 0; i < 2; i++)
#pragma unroll
                for (int e = 0; e < 4; e++) {
                    ah[i][e] = tf32_rna(araw[i][e]);
                    al[i][e] = tf32_rna(araw[i][e] - __uint_as_float(ah[i][e]));
                }

            uint4 B0 = bfrag[s * 64 + lane];        // n-half 0 (words 0-7)
            uint4 B1 = bfrag[s * 64 + 32 + lane];   // n-half 1 (words 8-15)

#pragma unroll
            for (int i = 0; i < 2; i++) {
                mma8(D[i][0], ah[i], B0.x, B0.y);   // ah*bh
                mma8(D[i][0], al[i], B0.x, B0.y);   // al*bh
                mma8(D[i][0], ah[i], B0.z, B0.w);   // ah*bl
                mma8(D[i][1], ah[i], B1.x, B1.y);
                mma8(D[i][1], al[i], B1.x, B1.y);
                mma8(D[i][1], ah[i], B1.z, B1.w);
            }
        }

        // Max over the 16 words, exp, store.
#pragma unroll
        for (int i = 0; i < 2; i++) {
            float mlo = fmaxf(fmaxf(D[i][0][0], D[i][0][1]),
                              fmaxf(D[i][1][0], D[i][1][1]));   // row g
            float mhi = fmaxf(fmaxf(D[i][0][2], D[i][0][3]),
                              fmaxf(D[i][1][2], D[i][1][3]));   // row g+8
            mlo = fmaxf(mlo, __shfl_xor_sync(0xffffffffu, mlo, 1));
            mlo = fmaxf(mlo, __shfl_xor_sync(0xffffffffu, mlo, 2));
            mhi = fmaxf(mhi, __shfl_xor_sync(0xffffffffu, mhi, 1));
            mhi = fmaxf(mhi, __shfl_xor_sync(0xffffffffu, mhi, 2));
            if (t == 0) {
                // sqrt(C) = 16 exactly
                g_emap[eb + m0 + 16 * i + g]     = expf(mlo * 0.0625f);
                g_emap[eb + m0 + 16 * i + g + 8] = expf(mhi * 0.0625f);
            }
        }
    }
}

// ---------------------------------------------------------------------------
// Kernel 2 (R8 structure — best measured pool, near DRAM roofline): lane owns
// output pair (2w2, 2w2+1); one LDG.128 per row per channel; the w-1 corner
// term comes from the left lane via one shfl_up per channel after the r-loop.
// grid (HP, TP, NB*2), block (32,8).
// ---------------------------------------------------------------------------
__global__ __launch_bounds__(256, 4) void pool_kernel(const float* __restrict__ vw,
                                                      float* __restrict__ out) {
    const int n     = blockIdx.z >> 1;
    const int chalf = blockIdx.z & 1;
    const int tp = blockIdx.y;
    const int hp = blockIdx.x;
    const int tid = threadIdx.y * 32 + threadIdx.x;

    __shared__ float4 wpk[9 * 14];   // {e[4w2], e[4w2+1], e[4w2+2], e[4w2+3]} per (r,w2)
    __shared__ float  wem[9 * 14];   // e[4w2-1]  (denominator only)
    __shared__ float  wrd[14 * 2];   // 1/denominator for outputs (2w2, 2w2+1)

    // Fill window-weight tables (126 items).
    if (tid < 126) {
        const int r  = tid / 14;
        const int w2 = tid - r * 14;
        const int dt = r / 3, dh = r - dt * 3;
        const int t = 2 * tp - 1 + dt;
        const int h = 2 * hp - 1 + dh;
        const bool rv = (t >= 0) && (h >= 0);
        const int tc = t > 0 ? t : 0;
        const int hc = h > 0 ? h : 0;
        const float* ep = g_emap + ((size_t)n * TT + tc) * SPLANE + (size_t)hc * WW;
        const int wb = 4 * w2;
        float em1 = (rv && wb > 0) ? ep[wb - 1] : 0.f;
        float e0 = rv ? ep[wb + 0] : 0.f;
        float e1 = rv ? ep[wb + 1] : 0.f;
        float e2 = rv ? ep[wb + 2] : 0.f;
        float e3 = rv ? ep[wb + 3] : 0.f;
        wpk[tid] = make_float4(e0, e1, e2, e3);
        wem[tid] = em1;
    }
    __syncthreads();
    if (tid < 28) {
        const int w2i = tid % 14;
        const int sel = tid / 14;
        float s = 0.f;
#pragma unroll
        for (int r = 0; r < 9; r++) {
            float4 f = wpk[r * 14 + w2i];
            s += sel ? (f.y + f.z + f.w) : (wem[r * 14 + w2i] + f.x + f.y);
        }
        wrd[w2i * 2 + sel] = 1.0f / s;
    }
    __syncthreads();

    const int lane = threadIdx.x;
    const int w2   = (lane & 15) < 14 ? (lane & 15) : 13;  // clamp
    const int csel = lane >> 4;                            // channel select 0/1
    const bool act = (lane & 15) < 14;

    const float rden0 = wrd[w2 * 2 + 0];
    const float rden1 = wrd[w2 * 2 + 1];

    int rowoff[9];
#pragma unroll
    for (int r = 0; r < 9; r++) {
        const int dt = r / 3, dh = r - dt * 3;
        const int t = 2 * tp - 1 + dt;
        const int h = 2 * hp - 1 + dh;
        const int tc = t > 0 ? t : 0;
        const int hc = h > 0 ? h : 0;
        rowoff[r] = (tc * HH + hc) * WW;
    }

    const float* basep = vw + (size_t)n * CC * PLANE + 4 * w2;
    float* outbase = out + (((size_t)n * CC * TP + tp) * HP + hp) * WP + 2 * w2;

    const int cbeg = chalf * (CC / 2);
    const ulonglong2* wpk2 = (const ulonglong2*)wpk;

    // 4 channels per warp-iteration: this lane handles cA=c0+2*csel, cB=cA+1.
    for (int c0 = cbeg + threadIdx.y * 4; c0 < cbeg + CC / 2; c0 += 32) {
        const int cA = c0 + 2 * csel;
        const float* pA = basep + (size_t)cA * PLANE;
        const float* pB = pA + PLANE;
        unsigned long long a0A = 0ull, a1A = 0ull, a0B = 0ull, a1B = 0ull;
        float sxA = 0.f, spA = 0.f, sxB = 0.f, spB = 0.f;
#pragma unroll
        for (int r = 0; r < 9; r++) {
            ulonglong2 xA = __ldg((const ulonglong2*)(pA + rowoff[r]));
            ulonglong2 xB = __ldg((const ulonglong2*)(pB + rowoff[r]));
            ulonglong2 wpr = wpk2[r * 14 + w2];   // .x = (e0,e1), .y = (e2,e3)
            a0A = fma2(wpr.x, xA.x, a0A);
            a1A = fma2(wpr.y, xA.y, a1A);
            a0B = fma2(wpr.x, xB.x, a0B);
            a1B = fma2(wpr.y, xB.y, a1B);
            sxA = fmaf(hi32(wpr.x), hi32(xA.x), sxA);   // e1*v1 -> own out1
            spA = fmaf(hi32(wpr.y), hi32(xA.y), spA);   // e3*v3 -> right nbr out0
            sxB = fmaf(hi32(wpr.x), hi32(xB.x), sxB);
            spB = fmaf(hi32(wpr.y), hi32(xB.y), spB);
        }
        float spAm = __shfl_up_sync(0xffffffffu, spA, 1);
        float spBm = __shfl_up_sync(0xffffffffu, spB, 1);
        if ((lane & 15) == 0) { spAm = 0.f; spBm = 0.f; }
        if (act) {
            float2 oA = make_float2((lo32(a0A) + hi32(a0A) + spAm) * rden0,
                                    (lo32(a1A) + hi32(a1A) + sxA) * rden1);
            float2 oB = make_float2((lo32(a0B) + hi32(a0B) + spBm) * rden0,
                                    (lo32(a1B) + hi32(a1B) + sxB) * rden1);
            *(float2*)(outbase + (size_t)cA * OPLANE) = oA;
            *(float2*)(outbase + (size_t)(cA + 1) * OPLANE) = oB;
        }
    }
}

extern "C" void kernel_launch(void* const* d_in, const int* in_sizes, int n_in,
                              void* d_out, int out_size) {
    const float* a0 = (const float*)d_in[0];
    const float* a1 = (const float*)d_in[1];
    // vw is the big tensor (51,380,224 elems); w is 16,384 elems.
    const float* vw   = (in_sizes[0] > in_sizes[1]) ? a0 : a1;
    const float* wmat = (in_sizes[0] > in_sizes[1]) ? a1 : a0;
    float* out = (float*)d_out;

    emap_kernel<<<dim3(7, TT, NB), dim3(32, 7)>>>(vw, wmat);
    pool_kernel<<<dim3(HP, TP, NB * 2), dim3(32, 8)>>>(vw, out);
}